// round 16
// baseline (speedup 1.0000x reference)
#include <cuda_runtime.h>
#include <cuda_fp16.h>
#include <math.h>
#include <stdint.h>

#define BB 2
#define SS 2048
#define DD 1024
#define HH 16
#define HDIM 64
#define MTOT (BB*SS)
// SCALE * log2(e): softmax via exp2
#define SCALE_Q 0.1803368801111601f
#define ONES2 0x3C003C00u   // half2(1.0, 1.0)

typedef __half h16;

// ---------------- device scratch (allocation-free rule) ----------------
__device__ __align__(256) h16 g_x[3][MTOT*DD];    // inputs fp16 (0=Q,1=K,2=V)
__device__ __align__(256) h16 g_wt[3][DD*DD];     // W transposed [n=h*64+e][k=d]
__device__ __align__(256) h16 g_wp[DD*DD];        // Wp [n][k] fp16
__device__ __align__(256) h16 g_q[BB*HH*SS*HDIM]; // [b,h,s,e], pre-scaled by SCALE*log2e
__device__ __align__(256) h16 g_k[BB*HH*SS*HDIM]; // [b,h,s,e]
__device__ __align__(256) h16 g_v[BB*HH*SS*HDIM]; // [b,h,s,e]
__device__ __align__(256) h16 g_c[MTOT*DD];       // attn concat out fp16

// ---------------- helpers ----------------
__device__ __forceinline__ uint32_t packh(float lo, float hi){
    __half2 p = __floats2half2_rn(lo, hi);
    return *(uint32_t*)&p;
}
__device__ __forceinline__ uint32_t ex2h2(uint32_t x){
    uint32_t r; asm("ex2.approx.f16x2 %0, %1;" : "=r"(r) : "r"(x)); return r;
}
__device__ __forceinline__ void ldsm4(uint32_t* r, uint32_t a){
    asm volatile("ldmatrix.sync.aligned.m8n8.x4.shared.b16 {%0,%1,%2,%3}, [%4];"
        : "=r"(r[0]),"=r"(r[1]),"=r"(r[2]),"=r"(r[3]) : "r"(a));
}
__device__ __forceinline__ void ldsm4t(uint32_t* r, uint32_t a){
    asm volatile("ldmatrix.sync.aligned.m8n8.x4.trans.shared.b16 {%0,%1,%2,%3}, [%4];"
        : "=r"(r[0]),"=r"(r[1]),"=r"(r[2]),"=r"(r[3]) : "r"(a));
}
__device__ __forceinline__ void mma16816(float* c, const uint32_t* a, uint32_t b0, uint32_t b1){
    asm volatile("mma.sync.aligned.m16n8k16.row.col.f32.f16.f16.f32 "
        "{%0,%1,%2,%3}, {%4,%5,%6,%7}, {%8,%9}, {%0,%1,%2,%3};"
        : "+f"(c[0]),"+f"(c[1]),"+f"(c[2]),"+f"(c[3])
        : "r"(a[0]),"r"(a[1]),"r"(a[2]),"r"(a[3]), "r"(b0),"r"(b1));
}
__device__ __forceinline__ void cp16(uint32_t s, const void* g){
    asm volatile("cp.async.cg.shared.global [%0], [%1], 16;" :: "r"(s), "l"(g));
}
#define CPCOMMIT() asm volatile("cp.async.commit_group;" ::: "memory")
#define CPWAIT0()  asm volatile("cp.async.wait_group 0;" ::: "memory")
#define CPWAIT1()  asm volatile("cp.async.wait_group 1;" ::: "memory")

// ---------------- merged conversions (R14, unchanged) ----------------
__global__ __launch_bounds__(256) void conv_all(
    const float* __restrict__ Q_in, const float* __restrict__ K_in,
    const float* __restrict__ V_in,
    const float* __restrict__ Wq, const float* __restrict__ Wk,
    const float* __restrict__ Wv, const float* __restrict__ Wp)
{
    const int z = blockIdx.z;
    const int tid = threadIdx.x;
    if (z < 3){
        const float* x = (z==0)?Q_in:(z==1)?K_in:V_in;
        int i = (blockIdx.y*128 + blockIdx.x)*256 + tid;
        float4 v0 = ((const float4*)x)[2*i];
        float4 v1 = ((const float4*)x)[2*i+1];
        uint4 o;
        o.x = packh(v0.x, v0.y); o.y = packh(v0.z, v0.w);
        o.z = packh(v1.x, v1.y); o.w = packh(v1.z, v1.w);
        ((uint4*)g_x[z])[i] = o;
    } else if (z < 6){
        if (blockIdx.x >= 16) return;
        __shared__ float t[64][65];
        const int sel = z - 3;
        const float* W = (sel==0)?Wq:(sel==1)?Wk:Wv;
        const int d0 = blockIdx.x*64, h = blockIdx.y;
        #pragma unroll
        for (int i = 0; i < 16; i++){
            int idx = tid + i*256, r = idx>>6, e = idx&63;
            t[r][e] = W[((size_t)h*DD + d0 + r)*HDIM + e];
        }
        __syncthreads();
        #pragma unroll
        for (int i = 0; i < 16; i++){
            int idx = tid + i*256, e = idx>>6, dc = idx&63;
            g_wt[sel][((size_t)(h*HDIM + e))*DD + d0 + dc] = __float2half_rn(t[dc][e]);
        }
    } else {
        if (blockIdx.x >= 16) return;
        const int c0 = blockIdx.x*64, r0 = blockIdx.y*64;
        #pragma unroll
        for (int i = 0; i < 8; i++){
            int idx = tid + i*256;
            int r = idx>>5, c2 = idx&31;
            float2 v = *(const float2*)&Wp[(size_t)(r0+r)*DD + c0 + c2*2];
            *(uint32_t*)&g_wp[(size_t)(r0+r)*DD + c0 + c2*2] = packh(v.x, v.y);
        }
    }
}

// ---------------- unified GEMM: 256 threads, 8 warps 64x32, 3-stage pipeline ----------------
// CTA tile 128m x 128n, BK=64. Triple-buffered (96KB), wait_group 1.
// Reg-limited to 2 CTAs/SM either way, so deeper smem costs no occupancy.
__global__ __launch_bounds__(256, 2) void gemm_mma(
    const float* __restrict__ bq, const float* __restrict__ bk,
    const float* __restrict__ bv, const float* __restrict__ bp,
    float* __restrict__ Out, int sel_base)
{
    extern __shared__ char smc[];
    const uint32_t smb = (uint32_t)__cvta_generic_to_shared(smc);
    const int sel = sel_base + blockIdx.z;
    const int m0 = blockIdx.x*128, n0 = blockIdx.y*128;
    const int tid = threadIdx.x, lane = tid&31, warp = tid>>5;
    const int wm = (warp&1)*64, wn = (warp>>1)*32;

    const h16* Ag = (sel<3)? g_x[sel] : g_c;
    const h16* Bg = (sel<3)? g_wt[sel] : g_wp;

    // preload chunks 0 and 1 into buffers 0 and 1 (separate commit groups)
    #pragma unroll
    for (int pc = 0; pc < 2; pc++){
        const uint32_t bo = (uint32_t)(pc*32768);
        #pragma unroll
        for (int i = 0; i < 4; i++){
            int u = tid + i*256, r = u>>3, c = u&7;
            uint32_t so = r*128 + ((c ^ (r&7))<<4);
            cp16(smb + bo + so,         Ag + (size_t)(m0+r)*DD + pc*64 + c*8);
            cp16(smb + bo + 16384 + so, Bg + (size_t)(n0+r)*DD + pc*64 + c*8);
        }
        CPCOMMIT();
    }

    const int ahi = lane>>4;
    const int bhi = (lane>>3)&1;
    int arow[4], brow[2];
    #pragma unroll
    for (int j = 0; j < 4; j++)  arow[j] = wm + j*16 + (lane&15);
    #pragma unroll
    for (int np = 0; np < 2; np++) brow[np] = wn + np*16 + (lane>>4)*8 + (lane&7);

    float acc[4][4][4] = {};

    int buf = 0;
    for (int kc = 0; kc < 16; kc++){
        if (kc == 15) CPWAIT0(); else CPWAIT1();
        __syncthreads();
        if (kc < 14){
            int nb = buf + 2; if (nb >= 3) nb -= 3;
            const uint32_t bo = (uint32_t)(nb*32768);
            #pragma unroll
            for (int i = 0; i < 4; i++){
                int u = tid + i*256, r = u>>3, c = u&7;
                uint32_t so = r*128 + ((c ^ (r&7))<<4);
                cp16(smb + bo + so,         Ag + (size_t)(m0+r)*DD + (kc+2)*64 + c*8);
                cp16(smb + bo + 16384 + so, Bg + (size_t)(n0+r)*DD + (kc+2)*64 + c*8);
            }
            CPCOMMIT();
        }
        const uint32_t ab = smb + (uint32_t)(buf*32768);
        const uint32_t bb = ab + 16384;
        #pragma unroll
        for (int kk = 0; kk < 4; kk++){
            uint32_t a[4][4];
            #pragma unroll
            for (int j = 0; j < 4; j++)
                ldsm4(a[j], ab + arow[j]*128 + (((kk*2+ahi) ^ (arow[j]&7))<<4));
            #pragma unroll
            for (int np = 0; np < 2; np++){
                uint32_t b[4];
                ldsm4(b, bb + brow[np]*128 + (((kk*2+bhi) ^ (brow[np]&7))<<4));
                #pragma unroll
                for (int j = 0; j < 4; j++){
                    mma16816(acc[j][2*np],   a[j], b[0], b[1]);
                    mma16816(acc[j][2*np+1], a[j], b[2], b[3]);
                }
            }
        }
        if (++buf == 3) buf = 0;
    }

    const float* bias = (sel==0)?bq : (sel==1)?bk : (sel==2)?bv : bp;
    const float scl = (sel==0) ? SCALE_Q : 1.0f;
    #pragma unroll
    for (int j = 0; j < 4; j++){
        const int rbase = m0 + wm + j*16 + (lane>>2);
        #pragma unroll
        for (int half = 0; half < 2; half++){
            const int m = rbase + half*8;
            const int bI = m>>11, s = m&(SS-1);
            #pragma unroll
            for (int nt = 0; nt < 4; nt++){
                const int n = n0 + wn + nt*8 + 2*(lane&3);
                float v0 = acc[j][nt][half*2]   + __ldg(&bias[n]);
                float v1 = acc[j][nt][half*2+1] + __ldg(&bias[n+1]);
                if (sel == 3){
                    *(float2*)&Out[(size_t)m*DD + n] = make_float2(v0, v1);
                } else {
                    h16* dst = (sel==0)?g_q : (sel==1)?g_k : g_v;
                    const int hh = n>>6, e = n&63;
                    size_t di = (((size_t)(bI*HH + hh))*SS + s)*HDIM + e;
                    *(uint32_t*)&dst[di] = packh(v0*scl, v1*scl);
                }
            }
        }
    }
}

// ---------------- flash attention (R12 winner, unchanged) ----------------
// 128 threads, 4 warps x 32 q-rows, Q tile 128, K tile 64, double-buffered. smem 48KB.
__global__ __launch_bounds__(128, 3) void attn_mma()
{
    extern __shared__ char smc[];
    const uint32_t smb = (uint32_t)__cvta_generic_to_shared(smc);
    const uint32_t Qb = smb;
    const uint32_t Kb[2] = { smb + 16384, smb + 32768 };
    const uint32_t Vb[2] = { smb + 24576, smb + 40960 };

    const int q0 = blockIdx.x*128, hid = blockIdx.y, bI = blockIdx.z;
    const int bh = bI*HH + hid;
    const int tid = threadIdx.x, lane = tid&31, warp = tid>>5;
    const int wm = warp*32;

    const h16* Qg = g_q + ((size_t)bh*SS + q0)*HDIM;
    const h16* Kg = g_k + (size_t)bh*SS*HDIM;
    const h16* Vg = g_v + (size_t)bh*SS*HDIM;

    #pragma unroll
    for (int i = 0; i < 8; i++){
        int u = tid + i*128, r = u>>3, c = u&7;
        cp16(Qb + r*128 + ((c ^ (r&7))<<4), Qg + (size_t)r*HDIM + c*8);
    }
    #pragma unroll
    for (int i = 0; i < 4; i++){
        int u = tid + i*128, r = u>>3, c = u&7;
        uint32_t so = r*128 + ((c ^ (r&7))<<4);
        cp16(Kb[0] + so, Kg + (size_t)r*HDIM + c*8);
        cp16(Vb[0] + so, Vg + (size_t)r*HDIM + c*8);
    }
    CPCOMMIT();

    const int ahi = lane>>4;
    const int bhi = (lane>>3)&1;
    const int vhi = lane>>4;
    int krow[4], vrow[4];
    #pragma unroll
    for (int np = 0; np < 4; np++) krow[np] = np*16 + (lane>>4)*8 + (lane&7);
    #pragma unroll
    for (int kk = 0; kk < 4; kk++) vrow[kk] = kk*16 + ((lane>>3)&1)*8 + (lane&7);

    CPWAIT0();
    __syncthreads();

    uint32_t qf[2][4][4];
    #pragma unroll
    for (int mi = 0; mi < 2; mi++){
        const int qrow = wm + mi*16 + (lane&15);
        #pragma unroll
        for (int kk = 0; kk < 4; kk++)
            ldsm4(qf[mi][kk], Qb + qrow*128 + (((kk*2+ahi) ^ (qrow&7))<<4));
    }

    float o[2][8][4] = {};
    float lacc[2][4] = {};

    for (int kt = 0; kt < 32; kt++){
        if (kt > 0){ CPWAIT0(); __syncthreads(); }
        if (kt < 31){
            const uint32_t kb = Kb[(kt+1)&1], vb = Vb[(kt+1)&1];
            const h16* Kn = Kg + (size_t)(kt+1)*64*HDIM;
            const h16* Vn = Vg + (size_t)(kt+1)*64*HDIM;
            #pragma unroll
            for (int i = 0; i < 4; i++){
                int u = tid + i*128, r = u>>3, c = u&7;
                uint32_t so = r*128 + ((c ^ (r&7))<<4);
                cp16(kb + so, Kn + (size_t)r*HDIM + c*8);
                cp16(vb + so, Vn + (size_t)r*HDIM + c*8);
            }
            CPCOMMIT();
        }
        const uint32_t kb = Kb[kt&1], vb = Vb[kt&1];

        float s[2][8][4] = {};
        #pragma unroll
        for (int kk = 0; kk < 4; kk++){
            #pragma unroll
            for (int np = 0; np < 4; np++){
                uint32_t k4[4];
                ldsm4(k4, kb + krow[np]*128 + (((kk*2+bhi) ^ (krow[np]&7))<<4));
                #pragma unroll
                for (int mi = 0; mi < 2; mi++){
                    mma16816(s[mi][2*np],   qf[mi][kk], k4[0], k4[1]);
                    mma16816(s[mi][2*np+1], qf[mi][kk], k4[2], k4[3]);
                }
            }
        }

        uint32_t h2[2][16];
        #pragma unroll
        for (int mi = 0; mi < 2; mi++){
            #pragma unroll
            for (int nt = 0; nt < 8; nt++){
                h2[mi][2*nt]   = ex2h2(packh(s[mi][nt][0], s[mi][nt][1]));
                h2[mi][2*nt+1] = ex2h2(packh(s[mi][nt][2], s[mi][nt][3]));
            }
        }

        #pragma unroll
        for (int kk = 0; kk < 4; kk++){
            const uint32_t* pa0 = &h2[0][4*kk];
            const uint32_t* pa1 = &h2[1][4*kk];
            mma16816(lacc[0], pa0, ONES2, ONES2);
            mma16816(lacc[1], pa1, ONES2, ONES2);
            #pragma unroll
            for (int np = 0; np < 4; np++){
                uint32_t v4[4];
                ldsm4t(v4, vb + vrow[kk]*128 + (((np*2+vhi) ^ (vrow[kk]&7))<<4));
                mma16816(o[0][2*np],   pa0, v4[0], v4[1]);
                mma16816(o[0][2*np+1], pa0, v4[2], v4[3]);
                mma16816(o[1][2*np],   pa1, v4[0], v4[1]);
                mma16816(o[1][2*np+1], pa1, v4[2], v4[3]);
            }
        }
    }

    #pragma unroll
    for (int mi = 0; mi < 2; mi++){
        const float inv0 = 1.f/lacc[mi][0], inv1 = 1.f/lacc[mi][2];
        const int sr = q0 + wm + mi*16 + (lane>>2);
        const int cb = 2*(lane&3);
        #pragma unroll
        for (int nt = 0; nt < 8; nt++){
            const int e = hid*HDIM + nt*8 + cb;
            #pragma unroll
            for (int half = 0; half < 2; half++){
                const int srow = sr + half*8;
                const float inv = half ? inv1 : inv0;
                size_t base = ((size_t)(bI*SS + srow))*DD + e;
                *(uint32_t*)&g_c[base] = packh(o[mi][nt][half*2]*inv, o[mi][nt][half*2+1]*inv);
            }
        }
    }
}

// ---------------- launch ----------------
// Inputs: K_in, V_in, Q_in, Wk, bk, Wq, bq, Wv, bv, Wp, bp
// Local idx 3 = outproj gemm_mma (profiled slot).
extern "C" void kernel_launch(void* const* d_in, const int* in_sizes, int n_in,
                              void* d_out, int out_size)
{
    const float* K_in = (const float*)d_in[0];
    const float* V_in = (const float*)d_in[1];
    const float* Q_in = (const float*)d_in[2];
    const float* Wk   = (const float*)d_in[3];
    const float* bk   = (const float*)d_in[4];
    const float* Wq   = (const float*)d_in[5];
    const float* bq   = (const float*)d_in[6];
    const float* Wv   = (const float*)d_in[7];
    const float* bv   = (const float*)d_in[8];
    const float* Wp   = (const float*)d_in[9];
    const float* bp   = (const float*)d_in[10];
    float* Out = (float*)d_out;

    static int init = 0;
    if (!init){
        cudaFuncSetAttribute(gemm_mma, cudaFuncAttributeMaxDynamicSharedMemorySize, 98304);
        cudaFuncSetAttribute(attn_mma, cudaFuncAttributeMaxDynamicSharedMemorySize, 49152);
        init = 1;
    }

    conv_all<<<dim3(128, 16, 7), 256>>>(Q_in, K_in, V_in, Wq, Wk, Wv, Wp);        // 0
    gemm_mma<<<dim3(MTOT/128, DD/128, 3), 256, 98304>>>(bq, bk, bv, bp, Out, 0);  // 1
    attn_mma<<<dim3(SS/128, HH, BB), 128, 49152>>>();                             // 2
    gemm_mma<<<dim3(MTOT/128, DD/128, 1), 256, 98304>>>(bq, bk, bv, bp, Out, 3);  // 3  <- ncu target
}

// round 17
// speedup vs baseline: 1.0275x; 1.0275x over previous
#include <cuda_runtime.h>
#include <cuda_fp16.h>
#include <math.h>
#include <stdint.h>

#define BB 2
#define SS 2048
#define DD 1024
#define HH 16
#define HDIM 64
#define MTOT (BB*SS)
#define NSPLIT 2
// SCALE * log2(e): softmax via exp2
#define SCALE_Q 0.1803368801111601f
#define ONES2 0x3C003C00u   // half2(1.0, 1.0)

typedef __half h16;

// ---------------- device scratch (allocation-free rule) ----------------
__device__ __align__(256) h16 g_x[3][MTOT*DD];    // inputs fp16 (0=Q,1=K,2=V)
__device__ __align__(256) h16 g_wt[3][DD*DD];     // W transposed [n=h*64+e][k=d]
__device__ __align__(256) h16 g_wp[DD*DD];        // Wp [n][k] fp16
__device__ __align__(256) h16 g_q[BB*HH*SS*HDIM]; // [b,h,s,e], pre-scaled by SCALE*log2e
__device__ __align__(256) h16 g_k[BB*HH*SS*HDIM]; // [b,h,s,e]
__device__ __align__(256) h16 g_v[BB*HH*SS*HDIM]; // [b,h,s,e]
__device__ __align__(256) h16 g_c[MTOT*DD];       // attn concat out fp16
__device__ __align__(256) float g_po[NSPLIT][BB*HH*SS*HDIM]; // partial O (unnormalized, fp32)
__device__ __align__(256) float g_pl[NSPLIT][BB*HH*SS];      // partial l

// ---------------- helpers ----------------
__device__ __forceinline__ uint32_t packh(float lo, float hi){
    __half2 p = __floats2half2_rn(lo, hi);
    return *(uint32_t*)&p;
}
__device__ __forceinline__ uint32_t ex2h2(uint32_t x){
    uint32_t r; asm("ex2.approx.f16x2 %0, %1;" : "=r"(r) : "r"(x)); return r;
}
__device__ __forceinline__ void ldsm4(uint32_t* r, uint32_t a){
    asm volatile("ldmatrix.sync.aligned.m8n8.x4.shared.b16 {%0,%1,%2,%3}, [%4];"
        : "=r"(r[0]),"=r"(r[1]),"=r"(r[2]),"=r"(r[3]) : "r"(a));
}
__device__ __forceinline__ void ldsm4t(uint32_t* r, uint32_t a){
    asm volatile("ldmatrix.sync.aligned.m8n8.x4.trans.shared.b16 {%0,%1,%2,%3}, [%4];"
        : "=r"(r[0]),"=r"(r[1]),"=r"(r[2]),"=r"(r[3]) : "r"(a));
}
__device__ __forceinline__ void mma16816(float* c, const uint32_t* a, uint32_t b0, uint32_t b1){
    asm volatile("mma.sync.aligned.m16n8k16.row.col.f32.f16.f16.f32 "
        "{%0,%1,%2,%3}, {%4,%5,%6,%7}, {%8,%9}, {%0,%1,%2,%3};"
        : "+f"(c[0]),"+f"(c[1]),"+f"(c[2]),"+f"(c[3])
        : "r"(a[0]),"r"(a[1]),"r"(a[2]),"r"(a[3]), "r"(b0),"r"(b1));
}
__device__ __forceinline__ void cp16(uint32_t s, const void* g){
    asm volatile("cp.async.cg.shared.global [%0], [%1], 16;" :: "r"(s), "l"(g));
}
#define CPCOMMIT() asm volatile("cp.async.commit_group;" ::: "memory")
#define CPWAIT0()  asm volatile("cp.async.wait_group 0;" ::: "memory")

// ---------------- merged conversions (R14, unchanged) ----------------
__global__ __launch_bounds__(256) void conv_all(
    const float* __restrict__ Q_in, const float* __restrict__ K_in,
    const float* __restrict__ V_in,
    const float* __restrict__ Wq, const float* __restrict__ Wk,
    const float* __restrict__ Wv, const float* __restrict__ Wp)
{
    const int z = blockIdx.z;
    const int tid = threadIdx.x;
    if (z < 3){
        const float* x = (z==0)?Q_in:(z==1)?K_in:V_in;
        int i = (blockIdx.y*128 + blockIdx.x)*256 + tid;
        float4 v0 = ((const float4*)x)[2*i];
        float4 v1 = ((const float4*)x)[2*i+1];
        uint4 o;
        o.x = packh(v0.x, v0.y); o.y = packh(v0.z, v0.w);
        o.z = packh(v1.x, v1.y); o.w = packh(v1.z, v1.w);
        ((uint4*)g_x[z])[i] = o;
    } else if (z < 6){
        if (blockIdx.x >= 16) return;
        __shared__ float t[64][65];
        const int sel = z - 3;
        const float* W = (sel==0)?Wq:(sel==1)?Wk:Wv;
        const int d0 = blockIdx.x*64, h = blockIdx.y;
        #pragma unroll
        for (int i = 0; i < 16; i++){
            int idx = tid + i*256, r = idx>>6, e = idx&63;
            t[r][e] = W[((size_t)h*DD + d0 + r)*HDIM + e];
        }
        __syncthreads();
        #pragma unroll
        for (int i = 0; i < 16; i++){
            int idx = tid + i*256, e = idx>>6, dc = idx&63;
            g_wt[sel][((size_t)(h*HDIM + e))*DD + d0 + dc] = __float2half_rn(t[dc][e]);
        }
    } else {
        if (blockIdx.x >= 16) return;
        const int c0 = blockIdx.x*64, r0 = blockIdx.y*64;
        #pragma unroll
        for (int i = 0; i < 8; i++){
            int idx = tid + i*256;
            int r = idx>>5, c2 = idx&31;
            float2 v = *(const float2*)&Wp[(size_t)(r0+r)*DD + c0 + c2*2];
            *(uint32_t*)&g_wp[(size_t)(r0+r)*DD + c0 + c2*2] = packh(v.x, v.y);
        }
    }
}

// ---------------- unified GEMM (R15 winner): 256 threads, 8 warps 64x32, double-buffered ----------------
__global__ __launch_bounds__(256, 2) void gemm_mma(
    const float* __restrict__ bq, const float* __restrict__ bk,
    const float* __restrict__ bv, const float* __restrict__ bp,
    float* __restrict__ Out, int sel_base)
{
    extern __shared__ char smc[];
    const uint32_t smb = (uint32_t)__cvta_generic_to_shared(smc);
    const int sel = sel_base + blockIdx.z;
    const int m0 = blockIdx.x*128, n0 = blockIdx.y*128;
    const int tid = threadIdx.x, lane = tid&31, warp = tid>>5;
    const int wm = (warp&1)*64, wn = (warp>>1)*32;

    const h16* Ag = (sel<3)? g_x[sel] : g_c;
    const h16* Bg = (sel<3)? g_wt[sel] : g_wp;

    #pragma unroll
    for (int i = 0; i < 4; i++){
        int u = tid + i*256, r = u>>3, c = u&7;
        uint32_t so = r*128 + ((c ^ (r&7))<<4);
        cp16(smb + so,         Ag + (size_t)(m0+r)*DD + c*8);
        cp16(smb + 16384 + so, Bg + (size_t)(n0+r)*DD + c*8);
    }
    CPCOMMIT();

    const int ahi = lane>>4;
    const int bhi = (lane>>3)&1;
    int arow[4], brow[2];
    #pragma unroll
    for (int j = 0; j < 4; j++)  arow[j] = wm + j*16 + (lane&15);
    #pragma unroll
    for (int np = 0; np < 2; np++) brow[np] = wn + np*16 + (lane>>4)*8 + (lane&7);

    float acc[4][4][4] = {};

    for (int kc = 0; kc < 16; kc++){
        CPWAIT0();
        __syncthreads();
        if (kc < 15){
            const uint32_t bo = (uint32_t)(((kc+1)&1)*32768);
            #pragma unroll
            for (int i = 0; i < 4; i++){
                int u = tid + i*256, r = u>>3, c = u&7;
                uint32_t so = r*128 + ((c ^ (r&7))<<4);
                cp16(smb + bo + so,         Ag + (size_t)(m0+r)*DD + (kc+1)*64 + c*8);
                cp16(smb + bo + 16384 + so, Bg + (size_t)(n0+r)*DD + (kc+1)*64 + c*8);
            }
            CPCOMMIT();
        }
        const uint32_t ab = smb + (uint32_t)((kc&1)*32768);
        const uint32_t bb = ab + 16384;
        #pragma unroll
        for (int kk = 0; kk < 4; kk++){
            uint32_t a[4][4];
            #pragma unroll
            for (int j = 0; j < 4; j++)
                ldsm4(a[j], ab + arow[j]*128 + (((kk*2+ahi) ^ (arow[j]&7))<<4));
            #pragma unroll
            for (int np = 0; np < 2; np++){
                uint32_t b[4];
                ldsm4(b, bb + brow[np]*128 + (((kk*2+bhi) ^ (brow[np]&7))<<4));
                #pragma unroll
                for (int j = 0; j < 4; j++){
                    mma16816(acc[j][2*np],   a[j], b[0], b[1]);
                    mma16816(acc[j][2*np+1], a[j], b[2], b[3]);
                }
            }
        }
    }

    const float* bias = (sel==0)?bq : (sel==1)?bk : (sel==2)?bv : bp;
    const float scl = (sel==0) ? SCALE_Q : 1.0f;
    #pragma unroll
    for (int j = 0; j < 4; j++){
        const int rbase = m0 + wm + j*16 + (lane>>2);
        #pragma unroll
        for (int half = 0; half < 2; half++){
            const int m = rbase + half*8;
            const int bI = m>>11, s = m&(SS-1);
            #pragma unroll
            for (int nt = 0; nt < 4; nt++){
                const int n = n0 + wn + nt*8 + 2*(lane&3);
                float v0 = acc[j][nt][half*2]   + __ldg(&bias[n]);
                float v1 = acc[j][nt][half*2+1] + __ldg(&bias[n+1]);
                if (sel == 3){
                    *(float2*)&Out[(size_t)m*DD + n] = make_float2(v0, v1);
                } else {
                    h16* dst = (sel==0)?g_q : (sel==1)?g_k : g_v;
                    const int hh = n>>6, e = n&63;
                    size_t di = (((size_t)(bI*HH + hh))*SS + s)*HDIM + e;
                    *(uint32_t*)&dst[di] = packh(v0*scl, v1*scl);
                }
            }
        }
    }
}

// ---------------- flash attention, split-KV x2 ----------------
// Grid (16, 16, BB*NSPLIT). 128 threads, 4 warps x 32 q-rows, K tile 64, 16 tiles per split.
// Writes unnormalized partial O (fp32) + partial l; combine kernel finishes.
__global__ __launch_bounds__(128, 3) void attn_mma()
{
    extern __shared__ char smc[];
    const uint32_t smb = (uint32_t)__cvta_generic_to_shared(smc);
    const uint32_t Qb = smb;
    const uint32_t Kb[2] = { smb + 16384, smb + 32768 };
    const uint32_t Vb[2] = { smb + 24576, smb + 40960 };

    const int q0 = blockIdx.x*128, hid = blockIdx.y;
    const int bI = blockIdx.z >> 1, sp = blockIdx.z & 1;
    const int bh = bI*HH + hid;
    const int tid = threadIdx.x, lane = tid&31, warp = tid>>5;
    const int wm = warp*32;

    const h16* Qg = g_q + ((size_t)bh*SS + q0)*HDIM;
    const h16* Kg = g_k + (size_t)bh*SS*HDIM + (size_t)sp*16*64*HDIM;
    const h16* Vg = g_v + (size_t)bh*SS*HDIM + (size_t)sp*16*64*HDIM;

    #pragma unroll
    for (int i = 0; i < 8; i++){
        int u = tid + i*128, r = u>>3, c = u&7;
        cp16(Qb + r*128 + ((c ^ (r&7))<<4), Qg + (size_t)r*HDIM + c*8);
    }
    #pragma unroll
    for (int i = 0; i < 4; i++){
        int u = tid + i*128, r = u>>3, c = u&7;
        uint32_t so = r*128 + ((c ^ (r&7))<<4);
        cp16(Kb[0] + so, Kg + (size_t)r*HDIM + c*8);
        cp16(Vb[0] + so, Vg + (size_t)r*HDIM + c*8);
    }
    CPCOMMIT();

    const int ahi = lane>>4;
    const int bhi = (lane>>3)&1;
    const int vhi = lane>>4;
    int krow[4], vrow[4];
    #pragma unroll
    for (int np = 0; np < 4; np++) krow[np] = np*16 + (lane>>4)*8 + (lane&7);
    #pragma unroll
    for (int kk = 0; kk < 4; kk++) vrow[kk] = kk*16 + ((lane>>3)&1)*8 + (lane&7);

    CPWAIT0();
    __syncthreads();

    uint32_t qf[2][4][4];
    #pragma unroll
    for (int mi = 0; mi < 2; mi++){
        const int qrow = wm + mi*16 + (lane&15);
        #pragma unroll
        for (int kk = 0; kk < 4; kk++)
            ldsm4(qf[mi][kk], Qb + qrow*128 + (((kk*2+ahi) ^ (qrow&7))<<4));
    }

    float o[2][8][4] = {};
    float lacc[2][4] = {};

    for (int kt = 0; kt < 16; kt++){
        if (kt > 0){ CPWAIT0(); __syncthreads(); }
        if (kt < 15){
            const uint32_t kb = Kb[(kt+1)&1], vb = Vb[(kt+1)&1];
            const h16* Kn = Kg + (size_t)(kt+1)*64*HDIM;
            const h16* Vn = Vg + (size_t)(kt+1)*64*HDIM;
            #pragma unroll
            for (int i = 0; i < 4; i++){
                int u = tid + i*128, r = u>>3, c = u&7;
                uint32_t so = r*128 + ((c ^ (r&7))<<4);
                cp16(kb + so, Kn + (size_t)r*HDIM + c*8);
                cp16(vb + so, Vn + (size_t)r*HDIM + c*8);
            }
            CPCOMMIT();
        }
        const uint32_t kb = Kb[kt&1], vb = Vb[kt&1];

        float s[2][8][4] = {};
        #pragma unroll
        for (int kk = 0; kk < 4; kk++){
            #pragma unroll
            for (int np = 0; np < 4; np++){
                uint32_t k4[4];
                ldsm4(k4, kb + krow[np]*128 + (((kk*2+bhi) ^ (krow[np]&7))<<4));
                #pragma unroll
                for (int mi = 0; mi < 2; mi++){
                    mma16816(s[mi][2*np],   qf[mi][kk], k4[0], k4[1]);
                    mma16816(s[mi][2*np+1], qf[mi][kk], k4[2], k4[3]);
                }
            }
        }

        uint32_t h2[2][16];
        #pragma unroll
        for (int mi = 0; mi < 2; mi++){
            #pragma unroll
            for (int nt = 0; nt < 8; nt++){
                h2[mi][2*nt]   = ex2h2(packh(s[mi][nt][0], s[mi][nt][1]));
                h2[mi][2*nt+1] = ex2h2(packh(s[mi][nt][2], s[mi][nt][3]));
            }
        }

        #pragma unroll
        for (int kk = 0; kk < 4; kk++){
            const uint32_t* pa0 = &h2[0][4*kk];
            const uint32_t* pa1 = &h2[1][4*kk];
            mma16816(lacc[0], pa0, ONES2, ONES2);
            mma16816(lacc[1], pa1, ONES2, ONES2);
            #pragma unroll
            for (int np = 0; np < 4; np++){
                uint32_t v4[4];
                ldsm4t(v4, vb + vrow[kk]*128 + (((np*2+vhi) ^ (vrow[kk]&7))<<4));
                mma16816(o[0][2*np],   pa0, v4[0], v4[1]);
                mma16816(o[0][2*np+1], pa0, v4[2], v4[3]);
                mma16816(o[1][2*np],   pa1, v4[0], v4[1]);
                mma16816(o[1][2*np+1], pa1, v4[2], v4[3]);
            }
        }
    }

    // epilogue: write UNNORMALIZED partial O (fp32) + partial l
    float* po = g_po[sp] + (size_t)bh*SS*HDIM;
    float* pl = g_pl[sp] + (size_t)bh*SS;
    #pragma unroll
    for (int mi = 0; mi < 2; mi++){
        const int r0 = q0 + wm + mi*16 + (lane>>2);
        if ((lane&3) == 0){
            pl[r0]     = lacc[mi][0];
            pl[r0 + 8] = lacc[mi][2];
        }
        const int cb = 2*(lane&3);
        #pragma unroll
        for (int nt = 0; nt < 8; nt++){
            const int e = nt*8 + cb;
            #pragma unroll
            for (int half = 0; half < 2; half++){
                const int srow = r0 + half*8;
                *(float2*)&po[(size_t)srow*HDIM + e] =
                    make_float2(o[mi][nt][half*2], o[mi][nt][half*2+1]);
            }
        }
    }
}

// ---------------- combine partials -> g_c (concat fp16) ----------------
// idx over [bh(5b)][s(11b)][e8(3b)]: 524288 threads, each handles 8 elems.
__global__ __launch_bounds__(256) void combine_attn()
{
    const int idx = blockIdx.x*256 + threadIdx.x;
    const int ew = idx & 7;
    const int s  = (idx >> 3) & (SS-1);
    const int bh = idx >> 14;
    const size_t base = ((size_t)bh*SS + s)*HDIM + ew*8;

    float4 a0 = *(const float4*)&g_po[0][base];
    float4 a1 = *(const float4*)&g_po[0][base + 4];
    float4 b0 = *(const float4*)&g_po[1][base];
    float4 b1 = *(const float4*)&g_po[1][base + 4];
    const float inv = 1.f / (g_pl[0][bh*SS + s] + g_pl[1][bh*SS + s]);

    uint4 out;
    out.x = packh((a0.x+b0.x)*inv, (a0.y+b0.y)*inv);
    out.y = packh((a0.z+b0.z)*inv, (a0.w+b0.w)*inv);
    out.z = packh((a1.x+b1.x)*inv, (a1.y+b1.y)*inv);
    out.w = packh((a1.z+b1.z)*inv, (a1.w+b1.w)*inv);

    const int b = bh >> 4, h = bh & 15;
    *(uint4*)&g_c[((size_t)(b*SS + s))*DD + h*HDIM + ew*8] = out;
}

// ---------------- launch ----------------
// Inputs: K_in, V_in, Q_in, Wk, bk, Wq, bq, Wv, bv, Wp, bp
extern "C" void kernel_launch(void* const* d_in, const int* in_sizes, int n_in,
                              void* d_out, int out_size)
{
    const float* K_in = (const float*)d_in[0];
    const float* V_in = (const float*)d_in[1];
    const float* Q_in = (const float*)d_in[2];
    const float* Wk   = (const float*)d_in[3];
    const float* bk   = (const float*)d_in[4];
    const float* Wq   = (const float*)d_in[5];
    const float* bq   = (const float*)d_in[6];
    const float* Wv   = (const float*)d_in[7];
    const float* bv   = (const float*)d_in[8];
    const float* Wp   = (const float*)d_in[9];
    const float* bp   = (const float*)d_in[10];
    float* Out = (float*)d_out;

    static int init = 0;
    if (!init){
        cudaFuncSetAttribute(gemm_mma, cudaFuncAttributeMaxDynamicSharedMemorySize, 65536);
        cudaFuncSetAttribute(attn_mma, cudaFuncAttributeMaxDynamicSharedMemorySize, 49152);
        init = 1;
    }

    conv_all<<<dim3(128, 16, 7), 256>>>(Q_in, K_in, V_in, Wq, Wk, Wv, Wp);        // 0
    gemm_mma<<<dim3(MTOT/128, DD/128, 3), 256, 65536>>>(bq, bk, bv, bp, Out, 0);  // 1
    attn_mma<<<dim3(SS/128, HH, BB*NSPLIT), 128, 49152>>>();                      // 2
    combine_attn<<<BB*HH*SS*HDIM/8/256, 256>>>();                                 // 3
    gemm_mma<<<dim3(MTOT/128, DD/128, 1), 256, 65536>>>(bq, bk, bv, bp, Out, 3);  // 4
}